// round 4
// baseline (speedup 1.0000x reference)
#include <cuda_runtime.h>
#include <math.h>

typedef unsigned long long ull;

#define Mdim 2048
#define Ndim 256
#define Kdim 256
#define ITERS 1000
#define NS_ITERS 12

// packed dual-fp32 FMA (sm_100a); ptxas never auto-fuses this from C++
#define FMA2(d, a, b, c) \
    asm("fma.rn.f32x2 %0, %1, %2, %3;" : "=l"(d) : "l"(a), "l"(b), "l"(c))

__device__ __forceinline__ ull pack2(float lo, float hi) {
    ull r; asm("mov.b64 %0, {%1, %2};" : "=l"(r) : "f"(lo), "f"(hi)); return r;
}
__device__ __forceinline__ void unpack2(float& lo, float& hi, ull v) {
    asm("mov.b64 {%0, %1}, %2;" : "=f"(lo), "=f"(hi) : "l"(v));
}

// Scratch (allocation-free rule: __device__ globals)
__device__ float g_G[Ndim * Ndim];
__device__ float g_Atb[Ndim * Kdim];
__device__ float g_X0[Ndim * Ndim];
__device__ float g_X1[Ndim * Ndim];
__device__ float g_Y[Ndim * Ndim];
__device__ float g_a[1];

// ---------------------------------------------------------------------------
// C = A^T X  (A: [M,N], X: [M,K], C: [N,K]), optionally += rho*I on diagonal
// ---------------------------------------------------------------------------
__global__ void atx_kernel(const float* __restrict__ A, const float* __restrict__ X,
                           float* __restrict__ C, const float* __restrict__ rho_p,
                           int addDiag)
{
    __shared__ float As[32][33];
    __shared__ float Xs[32][33];
    const int tx = threadIdx.x, ty = threadIdx.y;
    const int i0 = blockIdx.x * 32, j0 = blockIdx.y * 32;
    float acc = 0.f;
    for (int mt = 0; mt < Mdim; mt += 32) {
        As[ty][tx] = A[(mt + ty) * Ndim + i0 + tx];
        Xs[ty][tx] = X[(mt + ty) * Kdim + j0 + tx];
        __syncthreads();
#pragma unroll
        for (int mm = 0; mm < 32; mm++)
            acc = fmaf(As[mm][ty], Xs[mm][tx], acc);
        __syncthreads();
    }
    const int i = i0 + ty, j = j0 + tx;
    if (addDiag && i == j) acc += fabsf(rho_p[0]) + 1e-10f;
    C[i * Kdim + j] = acc;
}

// ---------------------------------------------------------------------------
// a = 1/||G||_inf  (G symmetric -> column sums == row sums)
// ---------------------------------------------------------------------------
__global__ void norm_kernel(const float* __restrict__ G, float* __restrict__ a_out)
{
    __shared__ float red[256];
    const int t = threadIdx.x;
    float s = 0.f;
    for (int j = 0; j < Ndim; j++) s += fabsf(G[j * Ndim + t]);
    red[t] = s;
    __syncthreads();
    for (int off = 128; off > 0; off >>= 1) {
        if (t < off) red[t] = fmaxf(red[t], red[t + off]);
        __syncthreads();
    }
    if (t == 0) a_out[0] = 1.0f / red[0];
}

__global__ void init_x_kernel(float* __restrict__ X, const float* __restrict__ a_p)
{
    const int idx = blockIdx.x * blockDim.x + threadIdx.x;
    const int i = idx >> 8, j = idx & 255;
    X[idx] = (i == j) ? a_p[0] : 0.f;
}

// ---------------------------------------------------------------------------
// 256x256x256 GEMM: mode 0: C = A@B ;  mode 1: C = 2A - A@B  (Newton-Schulz)
// ---------------------------------------------------------------------------
__global__ void gemm256_kernel(const float* __restrict__ A, const float* __restrict__ B,
                               float* __restrict__ C, int ns_mode)
{
    __shared__ float As[32][33];
    __shared__ float Bs[32][33];
    const int tx = threadIdx.x, ty = threadIdx.y;
    const int i = blockIdx.y * 32 + ty, j = blockIdx.x * 32 + tx;
    float acc = 0.f;
    for (int kt = 0; kt < Ndim; kt += 32) {
        As[ty][tx] = A[i * Ndim + kt + tx];
        Bs[ty][tx] = B[(kt + ty) * Ndim + j];
        __syncthreads();
#pragma unroll
        for (int mm = 0; mm < 32; mm++)
            acc = fmaf(As[ty][mm], Bs[mm][tx], acc);
        __syncthreads();
    }
    C[i * Ndim + j] = ns_mode ? fmaf(2.f, A[i * Ndim + j], -acc) : acc;
}

// ---------------------------------------------------------------------------
// Persistent ADMM, FFMA2 version.
// 128 blocks x 2 cols, 512 threads = rp(128 row-pairs) x q(4 j-quarters).
// Each thread: rows r0=2rp,r0+1, cols c0,c0+1; j-range [64q, 64q+64):
//   first 32 j from registers (iteration-invariant, packed (m_r0,m_r1)),
//   last 32 j from SMEM (natural float2 row-pair load, no packing).
// w is stored in SMEM pre-splatted per column: (w0,w0,w1,w1) -> one broadcast
// LDS.128 + two fma.rn.f32x2 per j. Cross-q reduction via SMEM float4.
// Uses Minv symmetry: Tpred[r] = sum_j Minv[j][r] * w[j].
// ---------------------------------------------------------------------------
__global__ void __launch_bounds__(512, 1) admm_kernel(
    const float* __restrict__ Minv, const float* __restrict__ Atb,
    const float* __restrict__ rho_p, const float* __restrict__ lam_p,
    float* __restrict__ out)
{
    extern __shared__ float sm[];
    float*  MinvS = sm;                               // 128 compact rows x 256
    float4* wbuf  = (float4*)(sm + 128 * Ndim);       // [2][256] splat pairs
    float4* p_s   = (float4*)(sm + 128 * Ndim + 2 * 256 * 4); // [3][128]

    const int tid = threadIdx.x;
    const int rp  = tid & 127;
    const int q   = tid >> 7;
    const int r0  = 2 * rp;
    const int c0  = blockIdx.x * 2;

    const float rho = fabsf(rho_p[0]) + 1e-10f;
    const float tau = fabsf(lam_p[0]) / rho;

    // Stage compact SMEM rows: global j with (j & 63) >= 32, compact row 32q+k
    {
        const float4* src = (const float4*)Minv;
        float4* dst = (float4*)MinvS;
        for (int idx = tid; idx < 128 * 64; idx += 512) {
            const int crow = idx >> 6, within = idx & 63;
            const int j = ((crow >> 5) << 6) + 32 + (crow & 31);
            dst[idx] = src[j * 64 + within];
        }
    }

    // Register rows: j = 64q + k, k in [0,32), packed (Minv[j][r0], Minv[j][r0+1])
    ull mreg[32];
#pragma unroll
    for (int k = 0; k < 32; k++) {
        const int j = 64 * q + k;
        mreg[k] = __ldg((const ull*)(Minv + j * Ndim + r0));
    }

    // State (q==0 threads own rows r0,r0+1 x cols c0,c0+1)
    float atb00 = 0.f, atb01 = 0.f, atb10 = 0.f, atb11 = 0.f;
    float z00 = 0.f, z01 = 0.f, z10 = 0.f, z11 = 0.f;
    float u00 = 0.f, u01 = 0.f, u10 = 0.f, u11 = 0.f;
    float tp00 = 0.f, tp01 = 0.f, tp10 = 0.f, tp11 = 0.f;
    if (q == 0) {
        atb00 = Atb[r0 * Kdim + c0];       atb01 = Atb[r0 * Kdim + c0 + 1];
        atb10 = Atb[(r0 + 1) * Kdim + c0]; atb11 = Atb[(r0 + 1) * Kdim + c0 + 1];
        // initial w = Atb (z=u=0), splat-stored
        wbuf[r0]     = make_float4(atb00, atb00, atb01, atb01);
        wbuf[r0 + 1] = make_float4(atb10, atb10, atb11, atb11);
    }
    __syncthreads();

    int b = 0;
    for (int it = 0; it < ITERS; ++it) {
        const ulonglong2* __restrict__ wb =
            (const ulonglong2*)(wbuf + b * 256);

        ull acc0 = 0ull;  // (sum rows r0,r1) for col c0   [0 bits == (0.f,0.f)]
        ull acc1 = 0ull;  // for col c1

#pragma unroll
        for (int k = 0; k < 32; k++) {                 // register rows
            const ulonglong2 wv = wb[64 * q + k];      // (w0,w0),(w1,w1)
            FMA2(acc0, mreg[k], wv.x, acc0);
            FMA2(acc1, mreg[k], wv.y, acc1);
        }
#pragma unroll
        for (int k = 0; k < 32; k++) {                 // SMEM rows
            const ull m2 = *(const ull*)(MinvS + (32 * q + k) * Ndim + r0);
            const ulonglong2 wv = wb[64 * q + 32 + k];
            FMA2(acc0, m2, wv.x, acc0);
            FMA2(acc1, m2, wv.y, acc1);
        }

        float a00, a10, a01, a11;
        unpack2(a00, a10, acc0);   // (row r0, row r1) col c0
        unpack2(a01, a11, acc1);   // col c1

        if (q) p_s[(q - 1) * 128 + rp] = make_float4(a00, a10, a01, a11);
        __syncthreads();

        if (q == 0) {
#pragma unroll
            for (int s = 0; s < 3; s++) {
                const float4 p = p_s[s * 128 + rp];
                a00 += p.x; a10 += p.y; a01 += p.z; a11 += p.w;
            }
            tp00 = a00; tp01 = a01; tp10 = a10; tp11 = a11;

            float g, zn;
            g = tp00 + u00; zn = fmaxf(g - tau, 0.f) + fminf(g + tau, 0.f);
            zn = fminf(fmaxf(zn, 0.f), 1.f); u00 += tp00 - zn; z00 = zn;
            g = tp01 + u01; zn = fmaxf(g - tau, 0.f) + fminf(g + tau, 0.f);
            zn = fminf(fmaxf(zn, 0.f), 1.f); u01 += tp01 - zn; z01 = zn;
            g = tp10 + u10; zn = fmaxf(g - tau, 0.f) + fminf(g + tau, 0.f);
            zn = fminf(fmaxf(zn, 0.f), 1.f); u10 += tp10 - zn; z10 = zn;
            g = tp11 + u11; zn = fmaxf(g - tau, 0.f) + fminf(g + tau, 0.f);
            zn = fminf(fmaxf(zn, 0.f), 1.f); u11 += tp11 - zn; z11 = zn;

            const float w00 = fmaf(rho, z00 - u00, atb00);
            const float w01 = fmaf(rho, z01 - u01, atb01);
            const float w10 = fmaf(rho, z10 - u10, atb10);
            const float w11 = fmaf(rho, z11 - u11, atb11);
            wbuf[(b ^ 1) * 256 + r0]     = make_float4(w00, w00, w01, w01);
            wbuf[(b ^ 1) * 256 + r0 + 1] = make_float4(w10, w10, w11, w11);
        }
        __syncthreads();
        b ^= 1;
    }

    if (q == 0) {
        out[r0 * Kdim + c0]           = tp00;
        out[r0 * Kdim + c0 + 1]       = tp01;
        out[(r0 + 1) * Kdim + c0]     = tp10;
        out[(r0 + 1) * Kdim + c0 + 1] = tp11;
    }
}

// ---------------------------------------------------------------------------
extern "C" void kernel_launch(void* const* d_in, const int* in_sizes, int n_in,
                              void* d_out, int out_size)
{
    // metadata order: T, s_A, s_mic_data, rho_param, lam_param
    const float* s_A   = (const float*)d_in[1];
    const float* s_mic = (const float*)d_in[2];
    const float* rho_p = (const float*)d_in[3];
    const float* lam_p = (const float*)d_in[4];
    float* out = (float*)d_out;

    float *G, *Atb, *X0, *X1, *Y, *ap;
    cudaGetSymbolAddress((void**)&G,   g_G);
    cudaGetSymbolAddress((void**)&Atb, g_Atb);
    cudaGetSymbolAddress((void**)&X0,  g_X0);
    cudaGetSymbolAddress((void**)&X1,  g_X1);
    cudaGetSymbolAddress((void**)&Y,   g_Y);
    cudaGetSymbolAddress((void**)&ap,  g_a);

    const size_t shmem = (size_t)(128 * Ndim) * sizeof(float)
                       + 2 * 256 * sizeof(float4) + 3 * 128 * sizeof(float4);
    cudaFuncSetAttribute(admm_kernel, cudaFuncAttributeMaxDynamicSharedMemorySize,
                         (int)shmem);

    dim3 tb(32, 32);
    dim3 gb(8, 8);
    atx_kernel<<<gb, tb>>>(s_A, s_A,   G,   rho_p, 1);
    atx_kernel<<<gb, tb>>>(s_A, s_mic, Atb, rho_p, 0);

    // Newton-Schulz inverse: X0 = I/||G||inf; X <- 2X - X@(G@X), 12 iters
    norm_kernel<<<1, 256>>>(G, ap);
    init_x_kernel<<<256, 256>>>(X0, ap);
    float* Xc = X0; float* Xn = X1;
    for (int i = 0; i < NS_ITERS; i++) {
        gemm256_kernel<<<gb, tb>>>(G,  Xc, Y,  0);  // Y  = G@X
        gemm256_kernel<<<gb, tb>>>(Xc, Y,  Xn, 1);  // Xn = 2X - X@Y
        float* t = Xc; Xc = Xn; Xn = t;
    }
    // NS_ITERS even -> result back in X0 (== Xc)

    admm_kernel<<<128, 512, shmem>>>(Xc, Atb, rho_p, lam_p, out);
}

// round 5
// speedup vs baseline: 1.4110x; 1.4110x over previous
#include <cuda_runtime.h>
#include <math.h>

typedef unsigned long long ull;

#define Mdim 2048
#define Ndim 256
#define Kdim 256
#define ITERS 1000
#define NS_ITERS 10
#define JREG 44            // j-rows per quarter held in registers
#define JSMEM 20           // j-rows per quarter from SMEM (44+20=64)

// packed dual-fp32 FMA; ptxas never auto-fuses this from C++
#define FMA2(d, a, b, c) \
    asm("fma.rn.f32x2 %0, %1, %2, %3;" : "=l"(d) : "l"(a), "l"(b), "l"(c))

__device__ __forceinline__ void unpack2(float& lo, float& hi, ull v) {
    asm("mov.b64 {%0, %1}, %2;" : "=f"(lo), "=f"(hi) : "l"(v));
}

// Scratch (allocation-free rule: __device__ globals)
__device__ float g_G[Ndim * Ndim];
__device__ float g_Atb[Ndim * Kdim];
__device__ float g_X0[Ndim * Ndim];
__device__ float g_X1[Ndim * Ndim];
__device__ float g_Y[Ndim * Ndim];
__device__ float g_a[1];

// ---------------------------------------------------------------------------
// C = A^T X  (A: [M,N], X: [M,K], C: [N,K]), optionally += rho*I on diagonal
// ---------------------------------------------------------------------------
__global__ void atx_kernel(const float* __restrict__ A, const float* __restrict__ X,
                           float* __restrict__ C, const float* __restrict__ rho_p,
                           int addDiag)
{
    __shared__ float As[32][33];
    __shared__ float Xs[32][33];
    const int tx = threadIdx.x, ty = threadIdx.y;
    const int i0 = blockIdx.x * 32, j0 = blockIdx.y * 32;
    float acc = 0.f;
    for (int mt = 0; mt < Mdim; mt += 32) {
        As[ty][tx] = A[(mt + ty) * Ndim + i0 + tx];
        Xs[ty][tx] = X[(mt + ty) * Kdim + j0 + tx];
        __syncthreads();
#pragma unroll
        for (int mm = 0; mm < 32; mm++)
            acc = fmaf(As[mm][ty], Xs[mm][tx], acc);
        __syncthreads();
    }
    const int i = i0 + ty, j = j0 + tx;
    if (addDiag && i == j) acc += fabsf(rho_p[0]) + 1e-10f;
    C[i * Kdim + j] = acc;
}

// a = 1/||G||_inf  (G symmetric)
__global__ void norm_kernel(const float* __restrict__ G, float* __restrict__ a_out)
{
    __shared__ float red[256];
    const int t = threadIdx.x;
    float s = 0.f;
    for (int j = 0; j < Ndim; j++) s += fabsf(G[j * Ndim + t]);
    red[t] = s;
    __syncthreads();
    for (int off = 128; off > 0; off >>= 1) {
        if (t < off) red[t] = fmaxf(red[t], red[t + off]);
        __syncthreads();
    }
    if (t == 0) a_out[0] = 1.0f / red[0];
}

__global__ void init_x_kernel(float* __restrict__ X, const float* __restrict__ a_p)
{
    const int idx = blockIdx.x * blockDim.x + threadIdx.x;
    const int i = idx >> 8, j = idx & 255;
    X[idx] = (i == j) ? a_p[0] : 0.f;
}

// 256^3 GEMM: mode 0: C = A@B ;  mode 1: C = 2A - A@B  (Newton-Schulz)
__global__ void gemm256_kernel(const float* __restrict__ A, const float* __restrict__ B,
                               float* __restrict__ C, int ns_mode)
{
    __shared__ float As[32][33];
    __shared__ float Bs[32][33];
    const int tx = threadIdx.x, ty = threadIdx.y;
    const int i = blockIdx.y * 32 + ty, j = blockIdx.x * 32 + tx;
    float acc = 0.f;
    for (int kt = 0; kt < Ndim; kt += 32) {
        As[ty][tx] = A[i * Ndim + kt + tx];
        Bs[ty][tx] = B[(kt + ty) * Ndim + j];
        __syncthreads();
#pragma unroll
        for (int mm = 0; mm < 32; mm++)
            acc = fmaf(As[ty][mm], Bs[mm][tx], acc);
        __syncthreads();
    }
    C[i * Ndim + j] = ns_mode ? fmaf(2.f, A[i * Ndim + j], -acc) : acc;
}

// ---------------------------------------------------------------------------
// Persistent ADMM v3: 128 blocks x 2 cols, 256 threads.
// Matvec: thread (rp=tid&63, q=tid>>6) computes rows 4rp..4rp+3 over
// j in [64q,64q+64): k<JREG from registers (ull pairs), rest from SMEM.
// w in SMEM pre-splatted per column: wbuf[j] = (w0,w0,w1,w1) -> one
// broadcast LDS.128 + 4 fma.rn.f32x2 per j.
// Epilogue: thread t owns row t's z/u/w state (fully parallel); reduction
// over the 4 q-partials via SMEM floats.
// Uses Minv symmetry: Tpred[r] = sum_j Minv[j][r] * w[j].
// ---------------------------------------------------------------------------
__global__ void __launch_bounds__(256, 1) admm_kernel(
    const float* __restrict__ Minv, const float* __restrict__ Atb,
    const float* __restrict__ rho_p, const float* __restrict__ lam_p,
    float* __restrict__ out)
{
    extern __shared__ float sm[];
    float*  MinvS = sm;                                  // 4*JSMEM rows x 256
    float4* wbuf  = (float4*)(sm + 4 * JSMEM * Ndim);    // [2][256] splat quads
    float*  ps    = (float*)(wbuf + 2 * 256);            // [2][4][256] partials

    const int tid = threadIdx.x;
    const int rp  = tid & 63;
    const int q   = tid >> 6;
    const int r0  = 4 * rp;
    const int c0  = blockIdx.x * 2;

    const float rho = fabsf(rho_p[0]) + 1e-10f;
    const float tau = fabsf(lam_p[0]) / rho;

    // Stage compact SMEM rows: global j = 64*(cr/JSMEM) + JREG + cr%JSMEM
    {
        const float4* src = (const float4*)Minv;
        float4* dst = (float4*)MinvS;
        for (int idx = tid; idx < 4 * JSMEM * 64; idx += 256) {
            const int cr = idx >> 6, within = idx & 63;
            const int j = 64 * (cr / JSMEM) + JREG + (cr % JSMEM);
            dst[idx] = src[j * 64 + within];
        }
    }

    // Register Minv: j = 64q + k, k < JREG; pairs (r0,r1) and (r2,r3)
    ull mreg[2 * JREG];
#pragma unroll
    for (int k = 0; k < JREG; k++) {
        const ulonglong2 v =
            __ldg((const ulonglong2*)(Minv + (64 * q + k) * Ndim + r0));
        mreg[2 * k]     = v.x;
        mreg[2 * k + 1] = v.y;
    }

    // Per-row state: thread t owns row t, cols c0,c0+1
    const float atb0 = Atb[tid * Kdim + c0];
    const float atb1 = Atb[tid * Kdim + c0 + 1];
    float u0 = 0.f, u1 = 0.f, tp0 = 0.f, tp1 = 0.f;
    wbuf[tid] = make_float4(atb0, atb0, atb1, atb1);   // w = Atb initially
    __syncthreads();

    const float* MsBase = MinvS + (JSMEM * q) * Ndim + r0;

    int b = 0;
    for (int it = 0; it < ITERS; ++it) {
        const ulonglong2* __restrict__ wb =
            (const ulonglong2*)(wbuf + b * 256) + 64 * q;

        ull a00 = 0ull, a10 = 0ull, a01 = 0ull, a11 = 0ull;
#pragma unroll
        for (int k = 0; k < JREG; k++) {
            const ulonglong2 wv = wb[k];
            FMA2(a00, mreg[2 * k],     wv.x, a00);
            FMA2(a10, mreg[2 * k + 1], wv.x, a10);
            FMA2(a01, mreg[2 * k],     wv.y, a01);
            FMA2(a11, mreg[2 * k + 1], wv.y, a11);
        }
#pragma unroll
        for (int k = 0; k < JSMEM; k++) {
            const ulonglong2 m = *(const ulonglong2*)(MsBase + k * Ndim);
            const ulonglong2 wv = wb[JREG + k];
            FMA2(a00, m.x, wv.x, a00);
            FMA2(a10, m.y, wv.x, a10);
            FMA2(a01, m.x, wv.y, a01);
            FMA2(a11, m.y, wv.y, a11);
        }

        float f0, f1, f2, f3;
        float* p0 = ps + q * 256 + r0;          // col c0 partials
        unpack2(f0, f1, a00); unpack2(f2, f3, a10);
        p0[0] = f0; p0[1] = f1; p0[2] = f2; p0[3] = f3;
        float* p1 = ps + 1024 + q * 256 + r0;   // col c1 partials
        unpack2(f0, f1, a01); unpack2(f2, f3, a11);
        p1[0] = f0; p1[1] = f1; p1[2] = f2; p1[3] = f3;
        __syncthreads();

        // Per-row reduce + update (all 256 threads, row = tid)
        tp0 = (ps[tid] + ps[256 + tid]) + (ps[512 + tid] + ps[768 + tid]);
        tp1 = (ps[1024 + tid] + ps[1280 + tid]) + (ps[1536 + tid] + ps[1792 + tid]);

        float g, zn, w0, w1;
        g = tp0 + u0; zn = fmaxf(g - tau, 0.f) + fminf(g + tau, 0.f);
        zn = fminf(fmaxf(zn, 0.f), 1.f); u0 += tp0 - zn;
        w0 = fmaf(rho, zn - u0, atb0);
        g = tp1 + u1; zn = fmaxf(g - tau, 0.f) + fminf(g + tau, 0.f);
        zn = fminf(fmaxf(zn, 0.f), 1.f); u1 += tp1 - zn;
        w1 = fmaf(rho, zn - u1, atb1);
        wbuf[(b ^ 1) * 256 + tid] = make_float4(w0, w0, w1, w1);
        __syncthreads();
        b ^= 1;
    }

    *(float2*)(out + tid * Kdim + c0) = make_float2(tp0, tp1);
}

// ---------------------------------------------------------------------------
extern "C" void kernel_launch(void* const* d_in, const int* in_sizes, int n_in,
                              void* d_out, int out_size)
{
    // metadata order: T, s_A, s_mic_data, rho_param, lam_param
    const float* s_A   = (const float*)d_in[1];
    const float* s_mic = (const float*)d_in[2];
    const float* rho_p = (const float*)d_in[3];
    const float* lam_p = (const float*)d_in[4];
    float* out = (float*)d_out;

    float *G, *Atb, *X0, *X1, *Y, *ap;
    cudaGetSymbolAddress((void**)&G,   g_G);
    cudaGetSymbolAddress((void**)&Atb, g_Atb);
    cudaGetSymbolAddress((void**)&X0,  g_X0);
    cudaGetSymbolAddress((void**)&X1,  g_X1);
    cudaGetSymbolAddress((void**)&Y,   g_Y);
    cudaGetSymbolAddress((void**)&ap,  g_a);

    const size_t shmem = (size_t)(4 * JSMEM * Ndim) * sizeof(float)
                       + 2 * 256 * sizeof(float4)
                       + 2 * 4 * 256 * sizeof(float);
    cudaFuncSetAttribute(admm_kernel, cudaFuncAttributeMaxDynamicSharedMemorySize,
                         (int)shmem);

    dim3 tb(32, 32);
    dim3 gb(8, 8);
    atx_kernel<<<gb, tb>>>(s_A, s_A,   G,   rho_p, 1);
    atx_kernel<<<gb, tb>>>(s_A, s_mic, Atb, rho_p, 0);

    // Newton-Schulz inverse: X0 = I/||G||inf; X <- 2X - X@(G@X)
    norm_kernel<<<1, 256>>>(G, ap);
    init_x_kernel<<<256, 256>>>(X0, ap);
    float* Xc = X0; float* Xn = X1;
    for (int i = 0; i < NS_ITERS; i++) {
        gemm256_kernel<<<gb, tb>>>(G,  Xc, Y,  0);  // Y  = G@X
        gemm256_kernel<<<gb, tb>>>(Xc, Y,  Xn, 1);  // Xn = 2X - X@Y
        float* t = Xc; Xc = Xn; Xn = t;
    }
    // NS_ITERS even -> result back in X0 (== Xc)

    admm_kernel<<<128, 256, shmem>>>(Xc, Atb, rho_p, lam_p, out);
}